// round 16
// baseline (speedup 1.0000x reference)
#include <cuda_runtime.h>
#include <cuda_bf16.h>
#include <math.h>
#include <stdint.h>

#define Bq 128
#define Lq 64
#define Tq 48
#define Eq 512
#define Hq 512
#define Vq 32000
#define G4 2048
#define KP 512
#define NTILES 250
#define LHALF 125
#define LSTRIDE 72
#define HB (Bq * Hq)
#define GVTILES ((Tq - 1) * 16)

// ---------------- scratch ----------------
__device__ __nv_bfloat16 g_G0[Bq * Lq * G4];
__device__ __nv_bfloat16 g_GV[(Tq - 1) * Bq * G4];
__device__ __nv_bfloat16 g_P1[4][Bq * G4];       // encoder L1 preact (t&3)
__device__ __nv_bfloat16 g_GIN[2][Bq * G4];      // decoder gates preact (s&1)
__device__ float g_M[G4 * 1024];
__device__ float g_bias2[G4];
__device__ float g_c1[HB], g_c2[HB];
__device__ __nv_bfloat16 g_S[Bq * Lq * Hq];
__device__ float g_dh[HB], g_dc[HB];
__device__ float g_nllbuf[(Tq - 1) * Bq];
__device__ float g_part[2][NTILES * Bq];
__device__ float g_tgtlogit[2][Bq];

// ---------------- sync flags ----------------
__device__ unsigned g_eflag[128];
__device__ unsigned g_dflag[64];

// ---------------- bf16 weights ----------------
__device__ __nv_bfloat16 g_Wih0b[G4 * KP], g_Whh0b[G4 * KP];
__device__ __nv_bfloat16 g_Wih1b[G4 * KP], g_Whh1b[G4 * KP];
__device__ __nv_bfloat16 g_dWihb[G4 * 1024], g_dWhhb[G4 * KP];
__device__ __nv_bfloat16 g_hidWb[Hq * 1024], g_initWb[Hq * 1024];
__device__ __nv_bfloat16 g_outWb[Vq * KP];
__device__ __nv_bfloat16 g_hidWT[1024 * 512];
__device__ __nv_bfloat16 g_Wdh[G4 * 512];
__device__ __nv_bfloat16 g_Wctx[G4 * 512];

// ---------------- compact gathered embeddings ----------------
__device__ __nv_bfloat16 g_xsB[Bq * Lq * Eq];
__device__ __nv_bfloat16 g_vembB[(Tq - 1) * Bq * Eq];

// ---------------- bf16 states ----------------
__device__ __nv_bfloat16 g_h1b[2][HB], g_h2b[2][HB], g_dhb[2][HB];
__device__ __nv_bfloat16 g_nh1b[4][HB];
__device__ __nv_bfloat16 g_c1b[HB], g_c2b[HB];
__device__ __nv_bfloat16 g_ctxb[2][HB];
__device__ __nv_bfloat16 g_avh[2][HB];

// ---------------- MMA helpers ----------------
__device__ __forceinline__ void ldsm4(unsigned* r, unsigned addr) {
    asm volatile("ldmatrix.sync.aligned.m8n8.x4.shared.b16 {%0,%1,%2,%3}, [%4];"
                 : "=r"(r[0]), "=r"(r[1]), "=r"(r[2]), "=r"(r[3]) : "r"(addr));
}
__device__ __forceinline__ void ldsm2(unsigned* r, unsigned addr) {
    asm volatile("ldmatrix.sync.aligned.m8n8.x2.shared.b16 {%0,%1}, [%2];"
                 : "=r"(r[0]), "=r"(r[1]) : "r"(addr));
}
__device__ __forceinline__ void mma16816(float* c, const unsigned* a, const unsigned* b) {
    asm volatile("mma.sync.aligned.m16n8k16.row.col.f32.bf16.bf16.f32 "
                 "{%0,%1,%2,%3}, {%4,%5,%6,%7}, {%8,%9}, {%0,%1,%2,%3};"
                 : "+f"(c[0]), "+f"(c[1]), "+f"(c[2]), "+f"(c[3])
                 : "r"(a[0]), "r"(a[1]), "r"(a[2]), "r"(a[3]), "r"(b[0]), "r"(b[1]));
}

__device__ __forceinline__ float sigm_f(float x) { return __fdividef(1.f, 1.f + __expf(-x)); }
__device__ __forceinline__ float tanh_f(float x) { return __fdividef(2.f, 1.f + __expf(-2.f * x)) - 1.f; }

// ---------------- one-shot flags ----------------
__device__ __forceinline__ void done_flag(unsigned* f) {
    __threadfence();
    __syncthreads();
    if (threadIdx.x == 0) atomicAdd(f, 1u);
}
__device__ __forceinline__ void wait_flag(unsigned* f, unsigned tgt) {
    if (threadIdx.x == 0) {
        while (*((volatile unsigned*)f) < tgt) __nanosleep(64);
    }
    __syncthreads();
}

// ============================================================
// core gates-layout MMA (shared by cell / preact bodies)
// ============================================================
__device__ __forceinline__ void gates_mma_core(
    float c[4][4][4], int nbase,
    const __nv_bfloat16* A0, const __nv_bfloat16* W0, int ldw0,
    const __nv_bfloat16* A1, const __nv_bfloat16* W1, int ldw1,
    int npairs, __nv_bfloat16* As, __nv_bfloat16* Bs)
{
    const int tid = threadIdx.x, lane = tid & 31, wid = tid >> 5;
    const int m0 = (wid >> 2) * 64, warp_n = wid & 3;
    const unsigned as_base = (unsigned)__cvta_generic_to_shared(As);
    const unsigned bs_base = (unsigned)__cvta_generic_to_shared(Bs);
    const int ldrow = tid >> 3, ldc8 = (tid & 7) * 8;

#pragma unroll
    for (int mi = 0; mi < 4; mi++)
#pragma unroll
        for (int ni = 0; ni < 4; ni++)
#pragma unroll
            for (int q = 0; q < 4; q++) c[mi][ni][q] = 0.f;

    uint4 ra[4], rb[4];
    const int total = npairs * 8;
    auto fetch = [&](int ch) {
        int p = ch >> 3, k0 = (ch & 7) * 64;
        const __nv_bfloat16* A = (p == 0) ? A0 : A1;
        const __nv_bfloat16* W = (p == 0) ? W0 : W1;
        int ldw = (p == 0) ? ldw0 : ldw1;
#pragma unroll
        for (int q = 0; q < 4; q++) {
            int row = q * 32 + ldrow;
            ra[q] = __ldcg(reinterpret_cast<const uint4*>(&A[(long)row * 512 + k0 + ldc8]));
            int wrow = ((row >> 5) * 512) + nbase + (row & 31);
            rb[q] = __ldg(reinterpret_cast<const uint4*>(&W[(long)wrow * ldw + k0 + ldc8]));
        }
    };
    fetch(0);
    for (int ch = 0; ch < total; ch++) {
        __syncthreads();
#pragma unroll
        for (int q = 0; q < 4; q++) {
            int row = q * 32 + ldrow;
            *reinterpret_cast<uint4*>(&As[row * LSTRIDE + ldc8]) = ra[q];
            *reinterpret_cast<uint4*>(&Bs[row * LSTRIDE + ldc8]) = rb[q];
        }
        __syncthreads();
        if (ch + 1 < total) fetch(ch + 1);
#pragma unroll
        for (int ks = 0; ks < 4; ks++) {
            int koff = ks * 16;
            unsigned a[4][4], b[4][2];
#pragma unroll
            for (int mi = 0; mi < 4; mi++) {
                int r = m0 + mi * 16 + (lane & 15);
                int ccol = koff + (lane >> 4) * 8;
                ldsm4(a[mi], as_base + (unsigned)(r * LSTRIDE + ccol) * 2u);
            }
#pragma unroll
            for (int ni = 0; ni < 4; ni++) {
                int r = ni * 32 + warp_n * 8 + (lane & 7);
                int ccol = koff + ((lane >> 3) & 1) * 8;
                ldsm2(b[ni], bs_base + (unsigned)(r * LSTRIDE + ccol) * 2u);
            }
#pragma unroll
            for (int mi = 0; mi < 4; mi++)
#pragma unroll
                for (int ni = 0; ni < 4; ni++) mma16816(c[mi][ni], a[mi], b[ni]);
        }
    }
}

// ============================================================
// gates GEMM + fused LSTM cell
// ============================================================
__device__ void gates_body(
    int nbase,
    const __nv_bfloat16* A0, const __nv_bfloat16* W0, int ldw0,
    const __nv_bfloat16* A1, const __nv_bfloat16* W1, int ldw1,
    int npairs,
    const __nv_bfloat16* initp, long initStride, const float* bias,
    const int* lens, int t,
    const __nv_bfloat16* hin, __nv_bfloat16* hout, float* cf,
    __nv_bfloat16* nh_out, __nv_bfloat16* S_out, float* hf_out,
    __nv_bfloat16* As, __nv_bfloat16* Bs)
{
    const int lane = threadIdx.x & 31, wid = threadIdx.x >> 5;
    const int m0 = (wid >> 2) * 64, warp_n = wid & 3;
    float c[4][4][4];
    gates_mma_core(c, nbase, A0, W0, ldw0, A1, W1, ldw1, npairs, As, Bs);

#pragma unroll
    for (int mi = 0; mi < 4; mi++) {
#pragma unroll
        for (int t2 = 0; t2 < 2; t2++) {
            int row = m0 + mi * 16 + (lane >> 2) + 8 * t2;
#pragma unroll
            for (int u = 0; u < 2; u++) {
                int j = nbase + warp_n * 8 + 2 * (lane & 3) + u;
                int e = 2 * t2 + u;
                float gi = c[mi][0][e], gf = c[mi][1][e], gg = c[mi][2][e], go = c[mi][3][e];
                if (initp) {
                    const __nv_bfloat16* ip = initp + (long)row * initStride;
                    gi += __bfloat162float(ip[j]);
                    gf += __bfloat162float(ip[512 + j]);
                    gg += __bfloat162float(ip[1024 + j]);
                    go += __bfloat162float(ip[1536 + j]);
                }
                if (bias) {
                    gi += bias[j]; gf += bias[512 + j]; gg += bias[1024 + j]; go += bias[1536 + j];
                }
                float i_ = sigm_f(gi), f_ = sigm_f(gf), tg = tanh_f(gg), o_ = sigm_f(go);
                int idx = row * 512 + j;
                float cv = __ldcg(&cf[idx]);
                float cn = f_ * cv + i_ * tg;
                float hn = o_ * tanh_f(cn);
                bool mk = lens ? (t < lens[row]) : true;
                if (nh_out) nh_out[idx] = __float2bfloat16_rn(hn);
                if (S_out) S_out[(long)row * Lq * 512 + (long)t * 512 + j] =
                    __float2bfloat16_rn(mk ? hn : 0.f);
                if (hf_out) hf_out[idx] = hn;
                if (mk) { cf[idx] = cn; hout[idx] = __float2bfloat16_rn(hn); }
                else {
                    unsigned short hv = __ldcg(reinterpret_cast<const unsigned short*>(&hin[idx]));
                    hout[idx] = *reinterpret_cast<__nv_bfloat16*>(&hv);
                }
            }
        }
    }
}

// ============================================================
// gates-layout preactivation GEMM: out = A@W^T + init? + bias? (bf16 out)
// ============================================================
__device__ void gates_pre_body(
    int nbase,
    const __nv_bfloat16* A, const __nv_bfloat16* W, int ldw,
    const __nv_bfloat16* initp, const float* bias,
    __nv_bfloat16* outBF,
    __nv_bfloat16* As, __nv_bfloat16* Bs)
{
    const int lane = threadIdx.x & 31, wid = threadIdx.x >> 5;
    const int m0 = (wid >> 2) * 64, warp_n = wid & 3;
    float c[4][4][4];
    gates_mma_core(c, nbase, A, W, ldw, nullptr, nullptr, 0, 1, As, Bs);

#pragma unroll
    for (int mi = 0; mi < 4; mi++) {
#pragma unroll
        for (int t2 = 0; t2 < 2; t2++) {
            int row = m0 + mi * 16 + (lane >> 2) + 8 * t2;
#pragma unroll
            for (int g = 0; g < 4; g++) {
#pragma unroll
                for (int u = 0; u < 2; u++) {
                    int j = nbase + warp_n * 8 + 2 * (lane & 3) + u;
                    int col = g * 512 + j;
                    float v = c[mi][g][2 * t2 + u];
                    if (initp) v += __bfloat162float(initp[(long)row * G4 + col]);
                    if (bias) v += bias[col];
                    outBF[(long)row * G4 + col] = __float2bfloat16_rn(v);
                }
            }
        }
    }
}

// ============================================================
// logits tile + exp-sum / target epilogue
// ============================================================
__device__ void logits_body(
    int tl, int ls, const __nv_bfloat16* avh, const float* out_b,
    const int* trg_tokens, __nv_bfloat16* As, __nv_bfloat16* Bs,
    int* stgt, float* red, float* partOut, float* tgtOut)
{
    const int tid = threadIdx.x, lane = tid & 31, wid = tid >> 5;
    const int m0 = (wid >> 2) * 64, warp_n = wid & 3;
    const int n0w = warp_n * 32;
    const int nblk0 = tl * 128;
    if (tid < 128) stgt[tid] = trg_tokens[tid * Tq + ls + 1];

    float c[4][4][4];
#pragma unroll
    for (int mi = 0; mi < 4; mi++)
#pragma unroll
        for (int ni = 0; ni < 4; ni++)
#pragma unroll
            for (int q = 0; q < 4; q++) c[mi][ni][q] = 0.f;

    const unsigned as_base = (unsigned)__cvta_generic_to_shared(As);
    const unsigned bs_base = (unsigned)__cvta_generic_to_shared(Bs);
    const int ldrow = tid >> 3, ldc8 = (tid & 7) * 8;

    uint4 ra[4], rb[4];
    auto fetch = [&](int kc) {
        int k0 = kc * 64;
#pragma unroll
        for (int q = 0; q < 4; q++) {
            int row = q * 32 + ldrow;
            ra[q] = *reinterpret_cast<const uint4*>(&avh[row * KP + k0 + ldc8]);
            rb[q] = __ldg(reinterpret_cast<const uint4*>(&g_outWb[(long)(nblk0 + row) * KP + k0 + ldc8]));
        }
    };
    fetch(0);
    for (int kc = 0; kc < 8; kc++) {
        __syncthreads();
#pragma unroll
        for (int q = 0; q < 4; q++) {
            int row = q * 32 + ldrow;
            *reinterpret_cast<uint4*>(&As[row * LSTRIDE + ldc8]) = ra[q];
            *reinterpret_cast<uint4*>(&Bs[row * LSTRIDE + ldc8]) = rb[q];
        }
        __syncthreads();
        if (kc + 1 < 8) fetch(kc + 1);
#pragma unroll
        for (int ks = 0; ks < 4; ks++) {
            int koff = ks * 16;
            unsigned a[4][4], b[4][2];
#pragma unroll
            for (int mi = 0; mi < 4; mi++) {
                int r = m0 + mi * 16 + (lane & 15);
                int ccol = koff + (lane >> 4) * 8;
                ldsm4(a[mi], as_base + (unsigned)(r * LSTRIDE + ccol) * 2u);
            }
#pragma unroll
            for (int ni = 0; ni < 4; ni++) {
                int r = n0w + ni * 8 + (lane & 7);
                int ccol = koff + ((lane >> 3) & 1) * 8;
                ldsm2(b[ni], bs_base + (unsigned)(r * LSTRIDE + ccol) * 2u);
            }
#pragma unroll
            for (int mi = 0; mi < 4; mi++)
#pragma unroll
                for (int ni = 0; ni < 4; ni++) mma16816(c[mi][ni], a[mi], b[ni]);
        }
    }
    __syncthreads();

    const int gid = lane >> 2, tig = lane & 3;
#pragma unroll
    for (int mi = 0; mi < 4; mi++) {
        int r0 = m0 + mi * 16 + gid;
        int r1 = r0 + 8;
        int t0 = stgt[r0], t1 = stgt[r1];
        float s0 = 0.f, s1 = 0.f;
#pragma unroll
        for (int ni = 0; ni < 4; ni++) {
            int n = nblk0 + n0w + ni * 8 + tig * 2;
            float b0 = out_b[n], b1 = out_b[n + 1];
            float l00 = c[mi][ni][0] + b0, l01 = c[mi][ni][1] + b1;
            float l10 = c[mi][ni][2] + b0, l11 = c[mi][ni][3] + b1;
            s0 += __expf(l00) + __expf(l01);
            s1 += __expf(l10) + __expf(l11);
            if (n == t0) tgtOut[r0] = l00;
            if (n + 1 == t0) tgtOut[r0] = l01;
            if (n == t1) tgtOut[r1] = l10;
            if (n + 1 == t1) tgtOut[r1] = l11;
        }
        s0 += __shfl_xor_sync(0xffffffffu, s0, 1);
        s0 += __shfl_xor_sync(0xffffffffu, s0, 2);
        s1 += __shfl_xor_sync(0xffffffffu, s1, 1);
        s1 += __shfl_xor_sync(0xffffffffu, s1, 2);
        if (tig == 0) { red[r0 * 4 + warp_n] = s0; red[r1 * 4 + warp_n] = s1; }
    }
    __syncthreads();
    if (tid < 128)
        partOut[tl * Bq + tid] = red[tid * 4] + red[tid * 4 + 1] + red[tid * 4 + 2] + red[tid * 4 + 3];
}

// ============================================================
// generic 128x128 tile, up to 2 pairs
// ============================================================
__device__ void tile128_body(
    const __nv_bfloat16* A0, const __nv_bfloat16* W0, int ldw0,
    const __nv_bfloat16* A1, const __nv_bfloat16* W1, int ldw1,
    int npairs, int wrow0,
    const float* bias, int biasOff,
    float* outF, __nv_bfloat16* outBF, long outStride, long outOff,
    __nv_bfloat16* As, __nv_bfloat16* Bs)
{
    const int tid = threadIdx.x, lane = tid & 31, wid = tid >> 5;
    const int m0 = (wid >> 2) * 64, warp_n = wid & 3;

    float c[4][4][4];
#pragma unroll
    for (int mi = 0; mi < 4; mi++)
#pragma unroll
        for (int ni = 0; ni < 4; ni++)
#pragma unroll
            for (int q = 0; q < 4; q++) c[mi][ni][q] = 0.f;

    const unsigned as_base = (unsigned)__cvta_generic_to_shared(As);
    const unsigned bs_base = (unsigned)__cvta_generic_to_shared(Bs);
    const int ldrow = tid >> 3, ldc8 = (tid & 7) * 8;

    uint4 ra[4], rb[4];
    const int total = npairs * 8;
    auto fetch = [&](int ch) {
        int p = ch >> 3, k0 = (ch & 7) * 64;
        const __nv_bfloat16* A = (p == 0) ? A0 : A1;
        const __nv_bfloat16* W = (p == 0) ? W0 : W1;
        int ldw = (p == 0) ? ldw0 : ldw1;
#pragma unroll
        for (int q = 0; q < 4; q++) {
            int row = q * 32 + ldrow;
            ra[q] = __ldcg(reinterpret_cast<const uint4*>(&A[(long)row * 512 + k0 + ldc8]));
            rb[q] = __ldg(reinterpret_cast<const uint4*>(&W[(long)(wrow0 + row) * ldw + k0 + ldc8]));
        }
    };
    fetch(0);
    for (int ch = 0; ch < total; ch++) {
        __syncthreads();
#pragma unroll
        for (int q = 0; q < 4; q++) {
            int row = q * 32 + ldrow;
            *reinterpret_cast<uint4*>(&As[row * LSTRIDE + ldc8]) = ra[q];
            *reinterpret_cast<uint4*>(&Bs[row * LSTRIDE + ldc8]) = rb[q];
        }
        __syncthreads();
        if (ch + 1 < total) fetch(ch + 1);
#pragma unroll
        for (int ks = 0; ks < 4; ks++) {
            int koff = ks * 16;
            unsigned a[4][4], b[4][2];
#pragma unroll
            for (int mi = 0; mi < 4; mi++) {
                int r = m0 + mi * 16 + (lane & 15);
                int ccol = koff + (lane >> 4) * 8;
                ldsm4(a[mi], as_base + (unsigned)(r * LSTRIDE + ccol) * 2u);
            }
#pragma unroll
            for (int ni = 0; ni < 4; ni++) {
                int r = warp_n * 32 + ni * 8 + (lane & 7);
                int ccol = koff + ((lane >> 3) & 1) * 8;
                ldsm2(b[ni], bs_base + (unsigned)(r * LSTRIDE + ccol) * 2u);
            }
#pragma unroll
            for (int mi = 0; mi < 4; mi++)
#pragma unroll
                for (int ni = 0; ni < 4; ni++) mma16816(c[mi][ni], a[mi], b[ni]);
        }
    }

#pragma unroll
    for (int mi = 0; mi < 4; mi++)
#pragma unroll
        for (int ni = 0; ni < 4; ni++)
#pragma unroll
            for (int t2 = 0; t2 < 2; t2++) {
                int gm = m0 + mi * 16 + (lane >> 2) + 8 * t2;
#pragma unroll
                for (int u = 0; u < 2; u++) {
                    int n = warp_n * 32 + ni * 8 + 2 * (lane & 3) + u;
                    float v = c[mi][ni][2 * t2 + u];
                    if (bias) v += bias[biasOff + n];
                    long oi = outOff + (long)gm * outStride + n;
                    if (outF) outF[oi] = v;
                    if (outBF) outBF[oi] = __float2bfloat16_rn(v);
                }
            }
}

// ============================================================
// encoder: lagged wavefront, grid 120
//  [0-15]   L0(2k)            -> eflag[3k]
//  [16-31]  L0(2k+1)  spin 3k
//  [32-47]  P1(2k-1)          -> eflag[3k+1]
//  [48-63]  P1(2k)    spin 3k
//  [64-79]  L1(2k-2)          -> eflag[3k+2]
//  [80-95]  L1(2k-1)  spin 3k+1, 3k+2
//  [96-119] GV riders
// ============================================================
__global__ __launch_bounds__(256) void enc2_k(
    int k, const int* __restrict__ src_lens,
    const float* __restrict__ enc_b1, const float* __restrict__ dec_b)
{
    __shared__ __nv_bfloat16 As[128 * LSTRIDE];
    __shared__ __nv_bfloat16 Bs[128 * LSTRIDE];
    const int blk = blockIdx.x;
    const int nbase = (blk & 15) * 32;
    if (blk < 16) {
        int t = 2 * k;
        if (t > Lq - 1) return;
        int p = t & 1;
        gates_body(nbase, g_h1b[p], g_Whh0b, 512,
                   nullptr, nullptr, 0, 1,
                   g_G0 + (long)t * G4, (long)Lq * G4, nullptr, src_lens, t,
                   g_h1b[p], g_h1b[1 - p], g_c1, g_nh1b[t & 3], nullptr, nullptr, As, Bs);
        done_flag(&g_eflag[k * 3]);
    } else if (blk < 32) {
        int t = 2 * k + 1;
        if (t > Lq - 1) return;
        wait_flag(&g_eflag[k * 3], 16);
        int p = t & 1;
        gates_body(nbase, g_h1b[p], g_Whh0b, 512,
                   nullptr, nullptr, 0, 1,
                   g_G0 + (long)t * G4, (long)Lq * G4, nullptr, src_lens, t,
                   g_h1b[p], g_h1b[1 - p], g_c1, g_nh1b[t & 3], nullptr, nullptr, As, Bs);
    } else if (blk < 48) {
        int t = 2 * k - 1;
        if (t < 0 || t > Lq - 1) return;
        gates_pre_body(nbase, g_nh1b[t & 3], g_Wih1b, 512,
                       nullptr, enc_b1, g_P1[t & 3], As, Bs);
        done_flag(&g_eflag[k * 3 + 1]);
    } else if (blk < 64) {
        int t = 2 * k;
        if (t > Lq - 1) return;
        wait_flag(&g_eflag[k * 3], 16);
        gates_pre_body(nbase, g_nh1b[t & 3], g_Wih1b, 512,
                       nullptr, enc_b1, g_P1[t & 3], As, Bs);
    } else if (blk < 80) {
        int t = 2 * k - 2;
        if (t < 0 || t > Lq - 1) return;
        int p = t & 1;
        gates_body(nbase, g_h2b[p], g_Whh1b, 512,
                   nullptr, nullptr, 0, 1,
                   g_P1[t & 3], (long)G4, nullptr, src_lens, t,
                   g_h2b[p], g_h2b[1 - p], g_c2, nullptr, g_S, nullptr, As, Bs);
        done_flag(&g_eflag[k * 3 + 2]);
    } else if (blk < 96) {
        int t = 2 * k - 1;
        if (t < 0 || t > Lq - 1) return;
        wait_flag(&g_eflag[k * 3 + 1], 16);
        if (2 * k - 2 >= 0) wait_flag(&g_eflag[k * 3 + 2], 16);
        int p = t & 1;
        gates_body(nbase, g_h2b[p], g_Whh1b, 512,
                   nullptr, nullptr, 0, 1,
                   g_P1[t & 3], (long)G4, nullptr, src_lens, t,
                   g_h2b[p], g_h2b[1 - p], g_c2, nullptr, g_S, nullptr, As, Bs);
    } else {
        int idx = k * 24 + blk - 96;
        if (idx >= GVTILES) return;
        int mt = idx >> 4, nt = idx & 15;
        tile128_body(g_vembB + (long)mt * 128 * 512, g_dWihb, 1024,
                     nullptr, nullptr, 0, 1, nt * 128,
                     dec_b, nt * 128,
                     nullptr, g_GV, G4, (long)mt * 128 * G4 + nt * 128, As, Bs);
    }
}

// ============================================================
// decoder single launch per step (grid 290):
//  [0-124]   logits(s-2)
//  [125-140] gates(s)      -> g_dflag[s]  (1 pair for s>=1)
//  [141-156] Pdh(s+1)      spin dflag[s]
//  [157-160] avh(s-1)
//  [161]     combine(s-3)
//  [162-289] attn(s)       spin dflag[s]
// ============================================================
__global__ __launch_bounds__(256) void dec1_k(
    int s, const int* __restrict__ trg_tokens, const int* __restrict__ src_lens,
    const int* __restrict__ trg_lens,
    const float* __restrict__ out_b, const float* __restrict__ hid_b)
{
    __shared__ __align__(16) char raw[128 * LSTRIDE * 4 + 2560];
    __nv_bfloat16* As = (__nv_bfloat16*)raw;
    __nv_bfloat16* Bs = As + 128 * LSTRIDE;
    int* stgt = (int*)(raw + 128 * LSTRIDE * 4);
    float* red = (float*)(raw + 128 * LSTRIDE * 4 + 512);
    const int blk = blockIdx.x;
    const int tid = threadIdx.x;

    if (blk < LHALF) {
        int ls = s - 2;
        if (ls < 0 || ls > Tq - 2) return;
        int par = ls & 1;
#pragma unroll
        for (int w = 0; w < 2; w++) {
            int tl = blk + LHALF * w;
            if (tl < NTILES)
                logits_body(tl, ls, g_avh[par], out_b, trg_tokens, As, Bs,
                            stgt, red, g_part[par], g_tgtlogit[par]);
        }
    } else if (blk < 141) {
        if (s > Tq - 2) return;
        int p = s & 1;
        int nbase = (blk - LHALF) * 32;
        if (s == 0) {
            gates_body(nbase, g_dhb[0], g_dWhhb, 512,
                       nullptr, nullptr, 0, 1,
                       g_GV, (long)G4, nullptr, nullptr, 0,
                       g_dhb[0], g_dhb[1], g_dc, nullptr, nullptr, g_dh, As, Bs);
        } else {
            gates_body(nbase, g_ctxb[(s - 1) & 1], g_Wctx, 512,
                       nullptr, nullptr, 0, 1,
                       g_GIN[s & 1], (long)G4, nullptr, nullptr, 0,
                       g_dhb[p], g_dhb[1 - p], g_dc, nullptr, nullptr, g_dh, As, Bs);
        }
        done_flag(&g_dflag[s]);
    } else if (blk < 157) {
        // Pdh(s+1) = dh(s)@Wdh + GV(s+1) + bias2 -> GIN[(s+1)&1]
        if (s > Tq - 2 || s + 1 > Tq - 2) return;
        wait_flag(&g_dflag[s], 16);
        int nbase = (blk - 141) * 32;
        gates_pre_body(nbase, g_dhb[(s + 1) & 1], g_Wdh, 512,
                       g_GV + (long)(s + 1) * Bq * G4, g_bias2,
                       g_GIN[(s + 1) & 1], As, Bs);
    } else if (blk < 161) {
        int sm1 = s - 1;
        if (sm1 < 0 || sm1 > Tq - 2) return;
        int nblk0 = (blk - 157) * 128;
        tile128_body(g_dhb[s & 1], g_hidWb, 1024,
                     g_ctxb[sm1 & 1], g_hidWb + 512, 1024, 2, nblk0,
                     hid_b, nblk0, nullptr,
                     g_avh[sm1 & 1], Hq, nblk0, As, Bs);
    } else if (blk == 161) {
        int ls = s - 3;
        if (ls < 0 || ls > Tq - 2) return;
        int par = ls & 1;
        int b = tid;
        if (b < 128) {
            float tot = 0.f;
            for (int i = 0; i < NTILES; i++) tot += g_part[par][i * Bq + b];
            float nll = logf(tot) - g_tgtlogit[par][b];
            g_nllbuf[ls * Bq + b] = ((ls + 1) < trg_lens[b]) ? -nll : 0.f;
        }
    } else {
        if (s > Tq - 2) return;
        wait_flag(&g_dflag[s], 16);
        int b = blk - 162;
        float* sh = (float*)raw;
        float* part = sh + 512;
        float* sc = part + 256;
        float* sinv = sc + 64;
        sh[tid] = __ldcg(&g_dh[(long)b * Hq + tid]);
        sh[tid + 256] = __ldcg(&g_dh[(long)b * Hq + tid + 256]);
        __syncthreads();
        int l = tid >> 2, q = tid & 3;
        const __nv_bfloat162* Sb =
            reinterpret_cast<const __nv_bfloat162*>(g_S + (long)b * Lq * Hq + (long)l * Hq + q * 128);
        float pv = 0.f;
#pragma unroll 16
        for (int kk = 0; kk < 64; kk++) {
            float2 v = __bfloat1622float2(__ldg(&Sb[kk]));
            pv = fmaf(sh[q * 128 + 2 * kk], v.x, pv);
            pv = fmaf(sh[q * 128 + 2 * kk + 1], v.y, pv);
        }
        part[l * 4 + q] = pv;
        __syncthreads();
        if (tid < Lq) {
            float sv = part[tid * 4] + part[tid * 4 + 1] + part[tid * 4 + 2] + part[tid * 4 + 3];
            if (tid >= src_lens[b]) sv = -1e9f;
            sc[tid] = __expf(sv);
        }
        __syncthreads();
        if (tid < 32) {
            float v = sc[tid] + sc[tid + 32];
            v += __shfl_down_sync(0xffffffffu, v, 16);
            v += __shfl_down_sync(0xffffffffu, v, 8);
            v += __shfl_down_sync(0xffffffffu, v, 4);
            v += __shfl_down_sync(0xffffffffu, v, 2);
            v += __shfl_down_sync(0xffffffffu, v, 1);
            if (tid == 0) *sinv = __fdividef(1.f, v);
        }
        __syncthreads();
        if (tid < Lq) sc[tid] *= *sinv;
        __syncthreads();
        {
            int j0 = tid * 2;
            const __nv_bfloat162* Sc =
                reinterpret_cast<const __nv_bfloat162*>(g_S + (long)b * Lq * Hq + j0);
            float ax = 0.f, ay = 0.f;
#pragma unroll 16
            for (int l2 = 0; l2 < Lq; l2++) {
                float2 v = __bfloat1622float2(__ldg(&Sc[(long)l2 * 256]));
                ax = fmaf(sc[l2], v.x, ax);
                ay = fmaf(sc[l2], v.y, ay);
            }
            __nv_bfloat162* cd =
                reinterpret_cast<__nv_bfloat162*>(&g_ctxb[s & 1][(long)b * Hq + j0]);
            *cd = __floats2bfloat162_rn(ax, ay);
        }
    }
}

// ============================================================
// standalone bf16 GEMM (pipelined, variable lda)
// ============================================================
__global__ __launch_bounds__(256) void hgemm_k(
    const __nv_bfloat16* __restrict__ A0, int lda,
    const __nv_bfloat16* __restrict__ W0, int ldw0,
    const __nv_bfloat16* __restrict__ A1, const __nv_bfloat16* __restrict__ W1, int ldw1,
    int npairs,
    const float* __restrict__ bias, int N,
    float* __restrict__ outRaw, float* __restrict__ outTanhF,
    __nv_bfloat16* __restrict__ outBF)
{
    __shared__ __nv_bfloat16 As[128 * LSTRIDE];
    __shared__ __nv_bfloat16 Bs[128 * LSTRIDE];
    const int tid = threadIdx.x, lane = tid & 31, wid = tid >> 5;
    const int m0 = (wid >> 2) * 64, warp_n = wid & 3;
    const int mblk0 = blockIdx.x * 128, nblk0 = blockIdx.y * 128;

    float c[4][4][4];
#pragma unroll
    for (int mi = 0; mi < 4; mi++)
#pragma unroll
        for (int ni = 0; ni < 4; ni++)
#pragma unroll
            for (int q = 0; q < 4; q++) c[mi][ni][q] = 0.f;

    const unsigned as_base = (unsigned)__cvta_generic_to_shared(As);
    const unsigned bs_base = (unsigned)__cvta_generic_to_shared(Bs);
    const int ldrow = tid >> 3, ldc8 = (tid & 7) * 8;

    uint4 ra[4], rb[4];
    const int total = npairs * 8;
    auto fetch = [&](int ch) {
        int p = ch >> 3, k0 = (ch & 7) * 64;
        const __nv_bfloat16* A = (p == 0) ? A0 : A1;
        const __nv_bfloat16* W = (p == 0) ? W0 : W1;
        int ldw = (p == 0) ? ldw0 : ldw1;
#pragma unroll
        for (int q = 0; q < 4; q++) {
            int row = q * 32 + ldrow;
            int gm = mblk0 + row;
            ra[q] = *reinterpret_cast<const uint4*>(&A[(long)gm * lda + k0 + ldc8]);
            rb[q] = *reinterpret_cast<const uint4*>(&W[(long)(nblk0 + row) * ldw + k0 + ldc8]);
        }
    };
    fetch(0);
    for (int ch = 0; ch < total; ch++) {
        __syncthreads();
#pragma unroll
        for (int q = 0; q < 4; q++) {
            int row = q * 32 + ldrow;
            *reinterpret_cast<uint4*>(&As[row * LSTRIDE + ldc8]) = ra[q];
            *reinterpret_cast<uint4*>(&Bs[row * LSTRIDE + ldc8]) = rb[q];
        }
        __syncthreads();
        if (ch + 1 < total) fetch(ch + 1);
#pragma unroll
        for (int ks = 0; ks < 4; ks++) {
            int koff = ks * 16;
            unsigned a[4][4], b[4][2];
#pragma unroll
            for (int mi = 0; mi < 4; mi++) {
                int r = m0 + mi * 16 + (lane & 15);
                int ccol = koff + (lane >> 4) * 8;
                ldsm4(a[mi], as_base + (unsigned)(r * LSTRIDE + ccol) * 2u);
            }
#pragma unroll
            for (int ni = 0; ni < 4; ni++) {
                int r = warp_n * 32 + ni * 8 + (lane & 7);
                int ccol = koff + ((lane >> 3) & 1) * 8;
                ldsm2(b[ni], bs_base + (unsigned)(r * LSTRIDE + ccol) * 2u);
            }
#pragma unroll
            for (int mi = 0; mi < 4; mi++)
#pragma unroll
                for (int ni = 0; ni < 4; ni++) mma16816(c[mi][ni], a[mi], b[ni]);
        }
    }

#pragma unroll
    for (int mi = 0; mi < 4; mi++)
#pragma unroll
        for (int ni = 0; ni < 4; ni++)
#pragma unroll
            for (int t2 = 0; t2 < 2; t2++) {
                int gm = mblk0 + m0 + mi * 16 + (lane >> 2) + 8 * t2;
#pragma unroll
                for (int u = 0; u < 2; u++) {
                    int n = nblk0 + warp_n * 32 + ni * 8 + 2 * (lane & 3) + u;
                    float v = c[mi][ni][2 * t2 + u];
                    long oi = (long)gm * N + n;
                    if (bias) v += bias[n];
                    if (outRaw) outRaw[oi] = v;
                    float tv = v;
                    if (outTanhF) { tv = tanhf(v); outTanhF[oi] = tv; }
                    if (outBF) outBF[oi] = __float2bfloat16_rn(outTanhF ? tv : v);
                }
            }
}

// ---------------- setup kernels ----------------
__device__ __forceinline__ void cvt8(const float* __restrict__ src,
                                     __nv_bfloat16* __restrict__ dst, long i)
{
    float4 v0 = *reinterpret_cast<const float4*>(src + i);
    float4 v1 = *reinterpret_cast<const float4*>(src + i + 4);
    __nv_bfloat162 r0 = __floats2bfloat162_rn(v0.x, v0.y);
    __nv_bfloat162 r1 = __floats2bfloat162_rn(v0.z, v0.w);
    __nv_bfloat162 r2 = __floats2bfloat162_rn(v1.x, v1.y);
    __nv_bfloat162 r3 = __floats2bfloat162_rn(v1.z, v1.w);
    uint4 o;
    o.x = *reinterpret_cast<unsigned*>(&r0);
    o.y = *reinterpret_cast<unsigned*>(&r1);
    o.z = *reinterpret_cast<unsigned*>(&r2);
    o.w = *reinterpret_cast<unsigned*>(&r3);
    *reinterpret_cast<uint4*>(dst + i) = o;
}

__global__ void f2bf_enc_k(const float* w0, const float* w1,
                           const float* w2, const float* w3)
{
    int seg = blockIdx.x >> 9;
    long i = ((long)(blockIdx.x & 511) * 256 + threadIdx.x) * 8;
    const float* srcs[4] = {w0, w1, w2, w3};
    __nv_bfloat16* dsts[4] = {g_Wih0b, g_Whh0b, g_Wih1b, g_Whh1b};
    cvt8(srcs[seg], dsts[seg], i);
}

__global__ void f2bf_dec_k(const float* dWih, const float* dWhh,
                           const float* hidW, const float* initW, const float* outW)
{
    int b = blockIdx.x;
    const float* src; __nv_bfloat16* dst; int rb;
    if (b < 1024)      { src = dWih;  dst = g_dWihb;  rb = b; }
    else if (b < 1536) { src = dWhh;  dst = g_dWhhb;  rb = b - 1024; }
    else if (b < 1792) { src = hidW;  dst = g_hidWb;  rb = b - 1536; }
    else if (b < 2048) { src = initW; dst = g_initWb; rb = b - 1792; }
    else               { src = outW;  dst = g_outWb;  rb = b - 2048; }
    long i = ((long)rb * 256 + threadIdx.x) * 8;
    cvt8(src, dst, i);
}

__global__ void transp_hidw_k(const float* __restrict__ hidW)
{
    __shared__ float tile[32][33];
    int k0 = blockIdx.x * 32;
    int j0 = blockIdx.y * 32;
    int tx = threadIdx.x & 31, ty = threadIdx.x >> 5;
#pragma unroll
    for (int m = 0; m < 4; m++)
        tile[ty + 8 * m][tx] = hidW[(long)(j0 + ty + 8 * m) * 1024 + k0 + tx];
    __syncthreads();
#pragma unroll
    for (int m = 0; m < 4; m++)
        g_hidWT[(long)(k0 + ty + 8 * m) * 512 + j0 + tx] =
            __float2bfloat16_rn(tile[tx][ty + 8 * m]);
}

__global__ void fold_k(const float* __restrict__ dWhh,
                       const float* __restrict__ dWih,
                       const float* __restrict__ hid_b)
{
    int b = blockIdx.x;
    if (b < 2048) {
        int n = b;
#pragma unroll
        for (int kk = 0; kk < 2; kk++) {
            int k = threadIdx.x + kk * 256;
            g_Wdh[(long)n * 512 + k] =
                __float2bfloat16_rn(dWhh[(long)n * 512 + k] + g_M[(long)n * 1024 + k]);
            g_Wctx[(long)n * 512 + k] =
                __float2bfloat16_rn(g_M[(long)n * 1024 + 512 + k]);
        }
    } else {
        int n = (b - 2048) * 256 + threadIdx.x;
        float acc = 0.f;
        for (int j = 0; j < 512; j++)
            acc = fmaf(dWih[(long)n * 1024 + 512 + j], hid_b[j], acc);
        g_bias2[n] = acc;
    }
}

__global__ void gather_src_k(const float* __restrict__ emb, const int* __restrict__ toks)
{
    int m = blockIdx.x;
    int tok = toks[m];
    const float2* src = reinterpret_cast<const float2*>(emb + (long)tok * Eq);
    __nv_bfloat162* dst = reinterpret_cast<__nv_bfloat162*>(g_xsB + (long)m * Eq);
    float2 v = src[threadIdx.x];
    dst[threadIdx.x] = __floats2bfloat162_rn(v.x, v.y);
}
__global__ void gather_trg_k(const float* __restrict__ emb, const int* __restrict__ toks)
{
    int m = blockIdx.x;
    int s = m >> 7, b = m & 127;
    int tok = toks[b * Tq + s];
    const float2* src = reinterpret_cast<const float2*>(emb + (long)tok * Eq);
    __nv_bfloat162* dst = reinterpret_cast<__nv_bfloat162*>(g_vembB + (long)m * Eq);
    float2 v = src[threadIdx.x];
    dst[threadIdx.x] = __floats2bfloat162_rn(v.x, v.y);
}

__global__ void zero_k()
{
    int i = blockIdx.x * 256 + threadIdx.x;
    if (i < HB) {
        g_h1b[0][i] = __float2bfloat16(0.f);
        g_h2b[0][i] = __float2bfloat16(0.f);
        g_c1[i] = 0.f; g_c2[i] = 0.f;
    }
    if (blockIdx.x == 0 && threadIdx.x < 128) g_eflag[threadIdx.x] = 0u;
    if (blockIdx.x == 1 && threadIdx.x < 64) g_dflag[threadIdx.x] = 0u;
}

__global__ void conv_c_k()
{
    int i = blockIdx.x * 256 + threadIdx.x;
    if (i < HB) {
        g_c1b[i] = __float2bfloat16_rn(g_c1[i]);
        g_c2b[i] = __float2bfloat16_rn(g_c2[i]);
    }
}

__global__ __launch_bounds__(256) void reduce_k(float* __restrict__ out)
{
    __shared__ float sm[256];
    float t = 0.f;
    for (int i = threadIdx.x; i < (Tq - 1) * Bq; i += 256) t += g_nllbuf[i];
    sm[threadIdx.x] = t;
    __syncthreads();
    for (int st = 128; st > 0; st >>= 1) {
        if (threadIdx.x < st) sm[threadIdx.x] += sm[threadIdx.x + st];
        __syncthreads();
    }
    if (threadIdx.x == 0) out[0] = sm[0];
}

// ---------------- launch ----------------
extern "C" void kernel_launch(void* const* d_in, const int* in_sizes, int n_in,
                              void* d_out, int out_size)
{
    const int*   src_tokens = (const int*)d_in[0];
    const int*   src_lens   = (const int*)d_in[1];
    const int*   trg_tokens = (const int*)d_in[2];
    const int*   trg_lens   = (const int*)d_in[3];
    const float* src_emb    = (const float*)d_in[4];
    const float* trg_emb    = (const float*)d_in[5];
    const float* enc_Wih0   = (const float*)d_in[6];
    const float* enc_Whh0   = (const float*)d_in[7];
    const float* enc_b0     = (const float*)d_in[8];
    const float* enc_Wih1   = (const float*)d_in[9];
    const float* enc_Whh1   = (const float*)d_in[10];
    const float* enc_b1     = (const float*)d_in[11];
    const float* dec_Wih    = (const float*)d_in[12];
    const float* dec_Whh    = (const float*)d_in[13];
    const float* dec_b      = (const float*)d_in[14];
    const float* hid_W      = (const float*)d_in[15];
    const float* hid_b      = (const float*)d_in[16];
    const float* out_W      = (const float*)d_in[17];
    const float* out_b      = (const float*)d_in[18];
    const float* init_W     = (const float*)d_in[19];
    const float* init_b     = (const float*)d_in[20];

    float *M, *dc, *dh;
    __nv_bfloat16 *G0, *Wih0b, *initWb, *c1b, *c2b, *dhb0, *xsB, *dWihb, *hidWT;
    cudaGetSymbolAddress((void**)&G0, g_G0);
    cudaGetSymbolAddress((void**)&M, g_M);
    cudaGetSymbolAddress((void**)&dc, g_dc);
    cudaGetSymbolAddress((void**)&dh, g_dh);
    cudaGetSymbolAddress((void**)&Wih0b, g_Wih0b);
    cudaGetSymbolAddress((void**)&initWb, g_initWb);
    cudaGetSymbolAddress((void**)&c1b, g_c1b);
    cudaGetSymbolAddress((void**)&c2b, g_c2b);
    cudaGetSymbolAddress((void**)&dhb0, g_dhb);
    cudaGetSymbolAddress((void**)&xsB, g_xsB);
    cudaGetSymbolAddress((void**)&dWihb, g_dWihb);
    cudaGetSymbolAddress((void**)&hidWT, g_hidWT);

    const int cb = (HB + 255) / 256;

    zero_k<<<cb, 256>>>();
    gather_src_k<<<Bq * Lq, 256>>>(src_emb, src_tokens);
    gather_trg_k<<<(Tq - 1) * Bq, 256>>>(trg_emb, trg_tokens);
    f2bf_enc_k<<<2048, 256>>>(enc_Wih0, enc_Whh0, enc_Wih1, enc_Whh1);
    f2bf_dec_k<<<10048, 256>>>(dec_Wih, dec_Whh, hid_W, init_W, out_W);
    transp_hidw_k<<<dim3(32, 16), 256>>>(hid_W);

    // M = dWih_r @ hidWT^T
    hgemm_k<<<dim3(16, 8), 256>>>(
        dWihb + 512, 1024, hidWT, 512,
        nullptr, nullptr, 0, 1,
        nullptr, 1024, M, nullptr, nullptr);
    fold_k<<<2056, 256>>>(dec_Whh, dec_Wih, hid_b);

    // G0 = xs @ Wih0^T + b0  (bf16 out)
    hgemm_k<<<dim3(Bq * Lq / 128, G4 / 128), 256>>>(
        xsB, 512, Wih0b, KP, nullptr, nullptr, 0, 1,
        enc_b0, G4, nullptr, nullptr, G0);

    // ---------------- encoder: lagged wavefront ----------------
    for (int k = 0; k <= Lq / 2; k++)
        enc2_k<<<120, 256>>>(k, src_lens, enc_b1, dec_b);

    // decoder init: c0 = [c1,c2] @ init_W^T + init_b ; h0 = tanh(c0)
    conv_c_k<<<cb, 256>>>();
    hgemm_k<<<dim3(1, Hq / 128), 256>>>(
        c1b, 512, initWb, 1024, c2b, initWb + 512, 1024, 2,
        init_b, Hq, dc, dh, dhb0);

    // ---------------- decoder: 1 launch per step ----------------
    for (int s = 0; s <= Tq + 1; s++)
        dec1_k<<<290, 256>>>(s, trg_tokens, src_lens, trg_lens, out_b, hid_b);

    reduce_k<<<1, 256>>>((float*)d_out);
}

// round 17
// speedup vs baseline: 1.1244x; 1.1244x over previous
#include <cuda_runtime.h>
#include <cuda_bf16.h>
#include <math.h>
#include <stdint.h>

#define Bq 128
#define Lq 64
#define Tq 48
#define Eq 512
#define Hq 512
#define Vq 32000
#define G4 2048
#define KP 512
#define NTILES 250
#define LHALF 125
#define LSTRIDE 72
#define HB (Bq * Hq)
#define GVTILES ((Tq - 1) * 16)

// ---------------- scratch ----------------
__device__ __nv_bfloat16 g_G0[Bq * Lq * G4];
__device__ __nv_bfloat16 g_GV[(Tq - 1) * Bq * G4];
__device__ float g_M[G4 * 1024];
__device__ float g_bias2[G4];
__device__ float g_c1[HB], g_c2[HB];
__device__ __nv_bfloat16 g_S[Bq * Lq * Hq];
__device__ float g_dh[HB], g_dc[HB];
__device__ float g_nllbuf[(Tq - 1) * Bq];
__device__ float g_part[2][NTILES * Bq];
__device__ float g_tgtlogit[2][Bq];

// ---------------- sync flags ----------------
__device__ unsigned g_eflag[80];
__device__ unsigned g_dflag[64];

// ---------------- bf16 weights ----------------
__device__ __nv_bfloat16 g_Wih0b[G4 * KP], g_Whh0b[G4 * KP];
__device__ __nv_bfloat16 g_Wih1b[G4 * KP], g_Whh1b[G4 * KP];
__device__ __nv_bfloat16 g_dWihb[G4 * 1024], g_dWhhb[G4 * KP];
__device__ __nv_bfloat16 g_hidWb[Hq * 1024], g_initWb[Hq * 1024];
__device__ __nv_bfloat16 g_outWb[Vq * KP];
__device__ __nv_bfloat16 g_hidWT[1024 * 512];
__device__ __nv_bfloat16 g_Wdh[G4 * 512];
__device__ __nv_bfloat16 g_Wctx[G4 * 512];

// ---------------- compact gathered embeddings ----------------
__device__ __nv_bfloat16 g_xsB[Bq * Lq * Eq];
__device__ __nv_bfloat16 g_vembB[(Tq - 1) * Bq * Eq];

// ---------------- bf16 states ----------------
__device__ __nv_bfloat16 g_h1b[2][HB], g_h2b[2][HB], g_dhb[2][HB];
__device__ __nv_bfloat16 g_nh1b[4][HB];
__device__ __nv_bfloat16 g_c1b[HB], g_c2b[HB];
__device__ __nv_bfloat16 g_ctxb[2][HB];
__device__ __nv_bfloat16 g_avh[2][HB];

// ---------------- MMA helpers ----------------
__device__ __forceinline__ void ldsm4(unsigned* r, unsigned addr) {
    asm volatile("ldmatrix.sync.aligned.m8n8.x4.shared.b16 {%0,%1,%2,%3}, [%4];"
                 : "=r"(r[0]), "=r"(r[1]), "=r"(r[2]), "=r"(r[3]) : "r"(addr));
}
__device__ __forceinline__ void ldsm2(unsigned* r, unsigned addr) {
    asm volatile("ldmatrix.sync.aligned.m8n8.x2.shared.b16 {%0,%1}, [%2];"
                 : "=r"(r[0]), "=r"(r[1]) : "r"(addr));
}
__device__ __forceinline__ void mma16816(float* c, const unsigned* a, const unsigned* b) {
    asm volatile("mma.sync.aligned.m16n8k16.row.col.f32.bf16.bf16.f32 "
                 "{%0,%1,%2,%3}, {%4,%5,%6,%7}, {%8,%9}, {%0,%1,%2,%3};"
                 : "+f"(c[0]), "+f"(c[1]), "+f"(c[2]), "+f"(c[3])
                 : "r"(a[0]), "r"(a[1]), "r"(a[2]), "r"(a[3]), "r"(b[0]), "r"(b[1]));
}

__device__ __forceinline__ float sigm_f(float x) { return __fdividef(1.f, 1.f + __expf(-x)); }
__device__ __forceinline__ float tanh_f(float x) { return __fdividef(2.f, 1.f + __expf(-2.f * x)) - 1.f; }

// ---------------- one-shot flags ----------------
__device__ __forceinline__ void done_flag(unsigned* f) {
    __threadfence();
    __syncthreads();
    if (threadIdx.x == 0) atomicAdd(f, 1u);
}
__device__ __forceinline__ void wait_flag(unsigned* f, unsigned tgt) {
    if (threadIdx.x == 0) {
        while (*((volatile unsigned*)f) < tgt) __nanosleep(64);
    }
    __syncthreads();
}

// ============================================================
// gates GEMM (pipelined) + fused LSTM cell (bf16 init tensor)
// ============================================================
__device__ void gates_body(
    int nbase,
    const __nv_bfloat16* A0, const __nv_bfloat16* W0, int ldw0,
    const __nv_bfloat16* A1, const __nv_bfloat16* W1, int ldw1,
    int npairs,
    const __nv_bfloat16* initp, long initStride, const float* bias,
    const int* lens, int t,
    const __nv_bfloat16* hin, __nv_bfloat16* hout, float* cf,
    __nv_bfloat16* nh_out, __nv_bfloat16* S_out, float* hf_out,
    __nv_bfloat16* As, __nv_bfloat16* Bs)
{
    const int tid = threadIdx.x, lane = tid & 31, wid = tid >> 5;
    const int m0 = (wid >> 2) * 64, warp_n = wid & 3;
    const unsigned as_base = (unsigned)__cvta_generic_to_shared(As);
    const unsigned bs_base = (unsigned)__cvta_generic_to_shared(Bs);
    const int ldrow = tid >> 3, ldc8 = (tid & 7) * 8;

    float c[4][4][4];
#pragma unroll
    for (int mi = 0; mi < 4; mi++)
#pragma unroll
        for (int ni = 0; ni < 4; ni++)
#pragma unroll
            for (int q = 0; q < 4; q++) c[mi][ni][q] = 0.f;

    uint4 ra[4], rb[4];
    const int total = npairs * 8;
    auto fetch = [&](int ch) {
        int p = ch >> 3, k0 = (ch & 7) * 64;
        const __nv_bfloat16* A = (p == 0) ? A0 : A1;
        const __nv_bfloat16* W = (p == 0) ? W0 : W1;
        int ldw = (p == 0) ? ldw0 : ldw1;
#pragma unroll
        for (int q = 0; q < 4; q++) {
            int row = q * 32 + ldrow;
            ra[q] = __ldcg(reinterpret_cast<const uint4*>(&A[(long)row * 512 + k0 + ldc8]));
            int wrow = ((row >> 5) * 512) + nbase + (row & 31);
            rb[q] = __ldg(reinterpret_cast<const uint4*>(&W[(long)wrow * ldw + k0 + ldc8]));
        }
    };
    fetch(0);
    for (int ch = 0; ch < total; ch++) {
        __syncthreads();
#pragma unroll
        for (int q = 0; q < 4; q++) {
            int row = q * 32 + ldrow;
            *reinterpret_cast<uint4*>(&As[row * LSTRIDE + ldc8]) = ra[q];
            *reinterpret_cast<uint4*>(&Bs[row * LSTRIDE + ldc8]) = rb[q];
        }
        __syncthreads();
        if (ch + 1 < total) fetch(ch + 1);
#pragma unroll
        for (int ks = 0; ks < 4; ks++) {
            int koff = ks * 16;
            unsigned a[4][4], b[4][2];
#pragma unroll
            for (int mi = 0; mi < 4; mi++) {
                int r = m0 + mi * 16 + (lane & 15);
                int ccol = koff + (lane >> 4) * 8;
                ldsm4(a[mi], as_base + (unsigned)(r * LSTRIDE + ccol) * 2u);
            }
#pragma unroll
            for (int ni = 0; ni < 4; ni++) {
                int r = ni * 32 + warp_n * 8 + (lane & 7);
                int ccol = koff + ((lane >> 3) & 1) * 8;
                ldsm2(b[ni], bs_base + (unsigned)(r * LSTRIDE + ccol) * 2u);
            }
#pragma unroll
            for (int mi = 0; mi < 4; mi++)
#pragma unroll
                for (int ni = 0; ni < 4; ni++) mma16816(c[mi][ni], a[mi], b[ni]);
        }
    }

    // cell epilogue
#pragma unroll
    for (int mi = 0; mi < 4; mi++) {
#pragma unroll
        for (int t2 = 0; t2 < 2; t2++) {
            int row = m0 + mi * 16 + (lane >> 2) + 8 * t2;
#pragma unroll
            for (int u = 0; u < 2; u++) {
                int j = nbase + warp_n * 8 + 2 * (lane & 3) + u;
                int e = 2 * t2 + u;
                float gi = c[mi][0][e], gf = c[mi][1][e], gg = c[mi][2][e], go = c[mi][3][e];
                if (initp) {
                    const __nv_bfloat16* ip = initp + (long)row * initStride;
                    gi += __bfloat162float(ip[j]);
                    gf += __bfloat162float(ip[512 + j]);
                    gg += __bfloat162float(ip[1024 + j]);
                    go += __bfloat162float(ip[1536 + j]);
                }
                if (bias) {
                    gi += bias[j]; gf += bias[512 + j]; gg += bias[1024 + j]; go += bias[1536 + j];
                }
                float i_ = sigm_f(gi), f_ = sigm_f(gf), tg = tanh_f(gg), o_ = sigm_f(go);
                int idx = row * 512 + j;
                float cv = __ldcg(&cf[idx]);
                float cn = f_ * cv + i_ * tg;
                float hn = o_ * tanh_f(cn);
                bool mk = lens ? (t < lens[row]) : true;
                if (nh_out) nh_out[idx] = __float2bfloat16_rn(hn);
                if (S_out) S_out[(long)row * Lq * 512 + (long)t * 512 + j] =
                    __float2bfloat16_rn(mk ? hn : 0.f);
                if (hf_out) hf_out[idx] = hn;
                if (mk) { cf[idx] = cn; hout[idx] = __float2bfloat16_rn(hn); }
                else {
                    unsigned short hv = __ldcg(reinterpret_cast<const unsigned short*>(&hin[idx]));
                    hout[idx] = *reinterpret_cast<__nv_bfloat16*>(&hv);
                }
            }
        }
    }
}

// ============================================================
// logits tile (pipelined) + exp-sum / target epilogue
// ============================================================
__device__ void logits_body(
    int tl, int ls, const __nv_bfloat16* avh, const float* out_b,
    const int* trg_tokens, __nv_bfloat16* As, __nv_bfloat16* Bs,
    int* stgt, float* red, float* partOut, float* tgtOut)
{
    const int tid = threadIdx.x, lane = tid & 31, wid = tid >> 5;
    const int m0 = (wid >> 2) * 64, warp_n = wid & 3;
    const int n0w = warp_n * 32;
    const int nblk0 = tl * 128;
    if (tid < 128) stgt[tid] = trg_tokens[tid * Tq + ls + 1];

    float c[4][4][4];
#pragma unroll
    for (int mi = 0; mi < 4; mi++)
#pragma unroll
        for (int ni = 0; ni < 4; ni++)
#pragma unroll
            for (int q = 0; q < 4; q++) c[mi][ni][q] = 0.f;

    const unsigned as_base = (unsigned)__cvta_generic_to_shared(As);
    const unsigned bs_base = (unsigned)__cvta_generic_to_shared(Bs);
    const int ldrow = tid >> 3, ldc8 = (tid & 7) * 8;

    uint4 ra[4], rb[4];
    auto fetch = [&](int kc) {
        int k0 = kc * 64;
#pragma unroll
        for (int q = 0; q < 4; q++) {
            int row = q * 32 + ldrow;
            ra[q] = *reinterpret_cast<const uint4*>(&avh[row * KP + k0 + ldc8]);
            rb[q] = __ldg(reinterpret_cast<const uint4*>(&g_outWb[(long)(nblk0 + row) * KP + k0 + ldc8]));
        }
    };
    fetch(0);
    for (int kc = 0; kc < 8; kc++) {
        __syncthreads();
#pragma unroll
        for (int q = 0; q < 4; q++) {
            int row = q * 32 + ldrow;
            *reinterpret_cast<uint4*>(&As[row * LSTRIDE + ldc8]) = ra[q];
            *reinterpret_cast<uint4*>(&Bs[row * LSTRIDE + ldc8]) = rb[q];
        }
        __syncthreads();
        if (kc + 1 < 8) fetch(kc + 1);
#pragma unroll
        for (int ks = 0; ks < 4; ks++) {
            int koff = ks * 16;
            unsigned a[4][4], b[4][2];
#pragma unroll
            for (int mi = 0; mi < 4; mi++) {
                int r = m0 + mi * 16 + (lane & 15);
                int ccol = koff + (lane >> 4) * 8;
                ldsm4(a[mi], as_base + (unsigned)(r * LSTRIDE + ccol) * 2u);
            }
#pragma unroll
            for (int ni = 0; ni < 4; ni++) {
                int r = n0w + ni * 8 + (lane & 7);
                int ccol = koff + ((lane >> 3) & 1) * 8;
                ldsm2(b[ni], bs_base + (unsigned)(r * LSTRIDE + ccol) * 2u);
            }
#pragma unroll
            for (int mi = 0; mi < 4; mi++)
#pragma unroll
                for (int ni = 0; ni < 4; ni++) mma16816(c[mi][ni], a[mi], b[ni]);
        }
    }
    __syncthreads();

    const int gid = lane >> 2, tig = lane & 3;
#pragma unroll
    for (int mi = 0; mi < 4; mi++) {
        int r0 = m0 + mi * 16 + gid;
        int r1 = r0 + 8;
        int t0 = stgt[r0], t1 = stgt[r1];
        float s0 = 0.f, s1 = 0.f;
#pragma unroll
        for (int ni = 0; ni < 4; ni++) {
            int n = nblk0 + n0w + ni * 8 + tig * 2;
            float b0 = out_b[n], b1 = out_b[n + 1];
            float l00 = c[mi][ni][0] + b0, l01 = c[mi][ni][1] + b1;
            float l10 = c[mi][ni][2] + b0, l11 = c[mi][ni][3] + b1;
            s0 += __expf(l00) + __expf(l01);
            s1 += __expf(l10) + __expf(l11);
            if (n == t0) tgtOut[r0] = l00;
            if (n + 1 == t0) tgtOut[r0] = l01;
            if (n == t1) tgtOut[r1] = l10;
            if (n + 1 == t1) tgtOut[r1] = l11;
        }
        s0 += __shfl_xor_sync(0xffffffffu, s0, 1);
        s0 += __shfl_xor_sync(0xffffffffu, s0, 2);
        s1 += __shfl_xor_sync(0xffffffffu, s1, 1);
        s1 += __shfl_xor_sync(0xffffffffu, s1, 2);
        if (tig == 0) { red[r0 * 4 + warp_n] = s0; red[r1 * 4 + warp_n] = s1; }
    }
    __syncthreads();
    if (tid < 128)
        partOut[tl * Bq + tid] = red[tid * 4] + red[tid * 4 + 1] + red[tid * 4 + 2] + red[tid * 4 + 3];
}

// ============================================================
// generic 128x128 tile, up to 2 pairs
// ============================================================
__device__ void tile128_body(
    const __nv_bfloat16* A0, const __nv_bfloat16* W0, int ldw0,
    const __nv_bfloat16* A1, const __nv_bfloat16* W1, int ldw1,
    int npairs, int wrow0,
    const float* bias, int biasOff,
    float* outF, __nv_bfloat16* outBF, long outStride, long outOff,
    __nv_bfloat16* As, __nv_bfloat16* Bs)
{
    const int tid = threadIdx.x, lane = tid & 31, wid = tid >> 5;
    const int m0 = (wid >> 2) * 64, warp_n = wid & 3;

    float c[4][4][4];
#pragma unroll
    for (int mi = 0; mi < 4; mi++)
#pragma unroll
        for (int ni = 0; ni < 4; ni++)
#pragma unroll
            for (int q = 0; q < 4; q++) c[mi][ni][q] = 0.f;

    const unsigned as_base = (unsigned)__cvta_generic_to_shared(As);
    const unsigned bs_base = (unsigned)__cvta_generic_to_shared(Bs);
    const int ldrow = tid >> 3, ldc8 = (tid & 7) * 8;

    uint4 ra[4], rb[4];
    const int total = npairs * 8;
    auto fetch = [&](int ch) {
        int p = ch >> 3, k0 = (ch & 7) * 64;
        const __nv_bfloat16* A = (p == 0) ? A0 : A1;
        const __nv_bfloat16* W = (p == 0) ? W0 : W1;
        int ldw = (p == 0) ? ldw0 : ldw1;
#pragma unroll
        for (int q = 0; q < 4; q++) {
            int row = q * 32 + ldrow;
            ra[q] = __ldcg(reinterpret_cast<const uint4*>(&A[(long)row * 512 + k0 + ldc8]));
            rb[q] = __ldg(reinterpret_cast<const uint4*>(&W[(long)(wrow0 + row) * ldw + k0 + ldc8]));
        }
    };
    fetch(0);
    for (int ch = 0; ch < total; ch++) {
        __syncthreads();
#pragma unroll
        for (int q = 0; q < 4; q++) {
            int row = q * 32 + ldrow;
            *reinterpret_cast<uint4*>(&As[row * LSTRIDE + ldc8]) = ra[q];
            *reinterpret_cast<uint4*>(&Bs[row * LSTRIDE + ldc8]) = rb[q];
        }
        __syncthreads();
        if (ch + 1 < total) fetch(ch + 1);
#pragma unroll
        for (int ks = 0; ks < 4; ks++) {
            int koff = ks * 16;
            unsigned a[4][4], b[4][2];
#pragma unroll
            for (int mi = 0; mi < 4; mi++) {
                int r = m0 + mi * 16 + (lane & 15);
                int ccol = koff + (lane >> 4) * 8;
                ldsm4(a[mi], as_base + (unsigned)(r * LSTRIDE + ccol) * 2u);
            }
#pragma unroll
            for (int ni = 0; ni < 4; ni++) {
                int r = warp_n * 32 + ni * 8 + (lane & 7);
                int ccol = koff + ((lane >> 3) & 1) * 8;
                ldsm2(b[ni], bs_base + (unsigned)(r * LSTRIDE + ccol) * 2u);
            }
#pragma unroll
            for (int mi = 0; mi < 4; mi++)
#pragma unroll
                for (int ni = 0; ni < 4; ni++) mma16816(c[mi][ni], a[mi], b[ni]);
        }
    }

#pragma unroll
    for (int mi = 0; mi < 4; mi++)
#pragma unroll
        for (int ni = 0; ni < 4; ni++)
#pragma unroll
            for (int t2 = 0; t2 < 2; t2++) {
                int gm = m0 + mi * 16 + (lane >> 2) + 8 * t2;
#pragma unroll
                for (int u = 0; u < 2; u++) {
                    int n = warp_n * 32 + ni * 8 + 2 * (lane & 3) + u;
                    float v = c[mi][ni][2 * t2 + u];
                    if (bias) v += bias[biasOff + n];
                    long oi = outOff + (long)gm * outStride + n;
                    if (outF) outF[oi] = v;
                    if (outBF) outBF[oi] = __float2bfloat16_rn(v);
                }
            }
}

// avh = dh@hidW_l + ctx@hidW_r + hid_b
__device__ void avh_tile_body(
    const __nv_bfloat16* A0, const __nv_bfloat16* A1,
    int nblk0, const float* hid_b, __nv_bfloat16* outBF,
    __nv_bfloat16* As, __nv_bfloat16* Bs)
{
    tile128_body(A0, g_hidWb, 1024, A1, g_hidWb + 512, 1024, 2, nblk0,
                 hid_b, nblk0, nullptr, outBF, Hq, nblk0, As, Bs);
}

// ============================================================
// generalized 128x128 GEMM tile for setup (variable lda, raw/bf16 out)
// ============================================================
__device__ void hg_tile(
    const __nv_bfloat16* A0, int lda, const __nv_bfloat16* W0, int ldw0,
    const float* bias, int N,
    float* outRaw, __nv_bfloat16* outBF,
    int mblk0, int nblk0,
    __nv_bfloat16* As, __nv_bfloat16* Bs)
{
    const int tid = threadIdx.x, lane = tid & 31, wid = tid >> 5;
    const int m0 = (wid >> 2) * 64, warp_n = wid & 3;

    float c[4][4][4];
#pragma unroll
    for (int mi = 0; mi < 4; mi++)
#pragma unroll
        for (int ni = 0; ni < 4; ni++)
#pragma unroll
            for (int q = 0; q < 4; q++) c[mi][ni][q] = 0.f;

    const unsigned as_base = (unsigned)__cvta_generic_to_shared(As);
    const unsigned bs_base = (unsigned)__cvta_generic_to_shared(Bs);
    const int ldrow = tid >> 3, ldc8 = (tid & 7) * 8;

    uint4 ra[4], rb[4];
    auto fetch = [&](int kc) {
        int k0 = kc * 64;
#pragma unroll
        for (int q = 0; q < 4; q++) {
            int row = q * 32 + ldrow;
            ra[q] = *reinterpret_cast<const uint4*>(&A0[(long)(mblk0 + row) * lda + k0 + ldc8]);
            rb[q] = *reinterpret_cast<const uint4*>(&W0[(long)(nblk0 + row) * ldw0 + k0 + ldc8]);
        }
    };
    fetch(0);
    for (int ch = 0; ch < 8; ch++) {
        __syncthreads();
#pragma unroll
        for (int q = 0; q < 4; q++) {
            int row = q * 32 + ldrow;
            *reinterpret_cast<uint4*>(&As[row * LSTRIDE + ldc8]) = ra[q];
            *reinterpret_cast<uint4*>(&Bs[row * LSTRIDE + ldc8]) = rb[q];
        }
        __syncthreads();
        if (ch + 1 < 8) fetch(ch + 1);
#pragma unroll
        for (int ks = 0; ks < 4; ks++) {
            int koff = ks * 16;
            unsigned a[4][4], b[4][2];
#pragma unroll
            for (int mi = 0; mi < 4; mi++) {
                int r = m0 + mi * 16 + (lane & 15);
                int ccol = koff + (lane >> 4) * 8;
                ldsm4(a[mi], as_base + (unsigned)(r * LSTRIDE + ccol) * 2u);
            }
#pragma unroll
            for (int ni = 0; ni < 4; ni++) {
                int r = warp_n * 32 + ni * 8 + (lane & 7);
                int ccol = koff + ((lane >> 3) & 1) * 8;
                ldsm2(b[ni], bs_base + (unsigned)(r * LSTRIDE + ccol) * 2u);
            }
#pragma unroll
            for (int mi = 0; mi < 4; mi++)
#pragma unroll
                for (int ni = 0; ni < 4; ni++) mma16816(c[mi][ni], a[mi], b[ni]);
        }
    }

#pragma unroll
    for (int mi = 0; mi < 4; mi++)
#pragma unroll
        for (int ni = 0; ni < 4; ni++)
#pragma unroll
            for (int t2 = 0; t2 < 2; t2++) {
                int gm = mblk0 + m0 + mi * 16 + (lane >> 2) + 8 * t2;
#pragma unroll
                for (int u = 0; u < 2; u++) {
                    int n = nblk0 + warp_n * 32 + ni * 8 + 2 * (lane & 3) + u;
                    float v = c[mi][ni][2 * t2 + u];
                    if (bias) v += bias[n];
                    long oi = (long)gm * N + n;
                    if (outRaw) outRaw[oi] = v;
                    if (outBF) outBF[oi] = __float2bfloat16_rn(v);
                }
            }
}

// ============================================================
// encoder: 2 wavefront steps per launch + GV riders (grid 88)
// ============================================================
__global__ __launch_bounds__(256) void enc2_k(
    int k, const int* __restrict__ src_lens,
    const float* __restrict__ enc_b1, const float* __restrict__ dec_b)
{
    __shared__ __nv_bfloat16 As[128 * LSTRIDE];
    __shared__ __nv_bfloat16 Bs[128 * LSTRIDE];
    const int blk = blockIdx.x;
    const int nbase = (blk & 15) * 32;
    if (blk < 16) {
        int t = 2 * k;
        if (t > Lq - 1) return;
        int p = t & 1;
        gates_body(nbase, g_h1b[p], g_Whh0b, 512,
                   nullptr, nullptr, 0, 1,
                   g_G0 + (long)t * G4, (long)Lq * G4, nullptr, src_lens, t,
                   g_h1b[p], g_h1b[1 - p], g_c1, g_nh1b[t & 3], nullptr, nullptr, As, Bs);
        done_flag(&g_eflag[k * 2]);
    } else if (blk < 32) {
        int t = 2 * k - 1;
        if (t < 0) return;
        int p = t & 1;
        gates_body(nbase, g_nh1b[t & 3], g_Wih1b, 512,
                   g_h2b[p], g_Whh1b, 512, 2,
                   nullptr, 0, enc_b1, src_lens, t,
                   g_h2b[p], g_h2b[1 - p], g_c2, nullptr, g_S, nullptr, As, Bs);
        done_flag(&g_eflag[k * 2 + 1]);
    } else if (blk < 48) {
        int t = 2 * k + 1;
        if (t > Lq - 1) return;
        wait_flag(&g_eflag[k * 2], 16);
        int p = t & 1;
        gates_body(nbase, g_h1b[p], g_Whh0b, 512,
                   nullptr, nullptr, 0, 1,
                   g_G0 + (long)t * G4, (long)Lq * G4, nullptr, src_lens, t,
                   g_h1b[p], g_h1b[1 - p], g_c1, g_nh1b[t & 3], nullptr, nullptr, As, Bs);
    } else if (blk < 64) {
        int t = 2 * k;
        if (t > Lq - 1) return;
        wait_flag(&g_eflag[k * 2], 16);
        if (k > 0) wait_flag(&g_eflag[k * 2 + 1], 16);
        int p = t & 1;
        gates_body(nbase, g_nh1b[t & 3], g_Wih1b, 512,
                   g_h2b[p], g_Whh1b, 512, 2,
                   nullptr, 0, enc_b1, src_lens, t,
                   g_h2b[p], g_h2b[1 - p], g_c2, nullptr, g_S, nullptr, As, Bs);
    } else {
        int idx = k * 24 + blk - 64;
        if (idx >= GVTILES) return;
        int mt = idx >> 4, nt = idx & 15;
        tile128_body(g_vembB + (long)mt * 128 * 512, g_dWihb, 1024,
                     nullptr, nullptr, 0, 1, nt * 128,
                     dec_b, nt * 128,
                     nullptr, g_GV, G4, (long)mt * 128 * G4 + nt * 128, As, Bs);
    }
}

// ============================================================
// decoder single launch per step (grid 274)
// ============================================================
__global__ __launch_bounds__(256) void dec1_k(
    int s, const int* __restrict__ trg_tokens, const int* __restrict__ src_lens,
    const int* __restrict__ trg_lens,
    const float* __restrict__ out_b, const float* __restrict__ hid_b)
{
    __shared__ __align__(16) char raw[128 * LSTRIDE * 4 + 2560];
    __nv_bfloat16* As = (__nv_bfloat16*)raw;
    __nv_bfloat16* Bs = As + 128 * LSTRIDE;
    int* stgt = (int*)(raw + 128 * LSTRIDE * 4);
    float* red = (float*)(raw + 128 * LSTRIDE * 4 + 512);
    const int blk = blockIdx.x;
    const int tid = threadIdx.x;

    if (blk < LHALF) {
        int ls = s - 2;
        if (ls < 0 || ls > Tq - 2) return;
        int par = ls & 1;
#pragma unroll
        for (int w = 0; w < 2; w++) {
            int tl = blk + LHALF * w;
            if (tl < NTILES)
                logits_body(tl, ls, g_avh[par], out_b, trg_tokens, As, Bs,
                            stgt, red, g_part[par], g_tgtlogit[par]);
        }
    } else if (blk < 141) {
        if (s > Tq - 2) return;
        int p = s & 1;
        int nbase = (blk - LHALF) * 32;
        if (s == 0) {
            gates_body(nbase, g_dhb[0], g_dWhhb, 512,
                       nullptr, nullptr, 0, 1,
                       g_GV, (long)G4, nullptr, nullptr, 0,
                       g_dhb[0], g_dhb[1], g_dc, nullptr, nullptr, g_dh, As, Bs);
        } else {
            gates_body(nbase, g_ctxb[(s - 1) & 1], g_Wctx, 512,
                       g_dhb[p], g_Wdh, 512, 2,
                       g_GV + (long)s * Bq * G4, (long)G4, g_bias2, nullptr, 0,
                       g_dhb[p], g_dhb[1 - p], g_dc, nullptr, nullptr, g_dh, As, Bs);
        }
        done_flag(&g_dflag[s]);
    } else if (blk < 145) {
        int sm1 = s - 1;
        if (sm1 < 0 || sm1 > Tq - 2) return;
        int nblk0 = (blk - 141) * 128;
        avh_tile_body(g_dhb[s & 1], g_ctxb[sm1 & 1], nblk0, hid_b,
                      g_avh[sm1 & 1], As, Bs);
    } else if (blk == 145) {
        int ls = s - 3;
        if (ls < 0 || ls > Tq - 2) return;
        int par = ls & 1;
        int b = tid;
        if (b < 128) {
            float tot = 0.f;
            for (int i = 0; i < NTILES; i++) tot += g_part[par][i * Bq + b];
            float nll = logf(tot) - g_tgtlogit[par][b];
            g_nllbuf[ls * Bq + b] = ((ls + 1) < trg_lens[b]) ? -nll : 0.f;
        }
    } else {
        if (s > Tq - 2) return;
        wait_flag(&g_dflag[s], 16);
        int b = blk - 146;
        float* sh = (float*)raw;
        float* part = sh + 512;
        float* sc = part + 256;
        float* sinv = sc + 64;
        sh[tid] = __ldcg(&g_dh[(long)b * Hq + tid]);
        sh[tid + 256] = __ldcg(&g_dh[(long)b * Hq + tid + 256]);
        __syncthreads();
        int l = tid >> 2, q = tid & 3;
        const __nv_bfloat162* Sb =
            reinterpret_cast<const __nv_bfloat162*>(g_S + (long)b * Lq * Hq + (long)l * Hq + q * 128);
        float pv = 0.f;
#pragma unroll 16
        for (int kk = 0; kk < 64; kk++) {
            float2 v = __bfloat1622float2(__ldg(&Sb[kk]));
            pv = fmaf(sh[q * 128 + 2 * kk], v.x, pv);
            pv = fmaf(sh[q * 128 + 2 * kk + 1], v.y, pv);
        }
        part[l * 4 + q] = pv;
        __syncthreads();
        if (tid < Lq) {
            float sv = part[tid * 4] + part[tid * 4 + 1] + part[tid * 4 + 2] + part[tid * 4 + 3];
            if (tid >= src_lens[b]) sv = -1e9f;
            sc[tid] = __expf(sv);
        }
        __syncthreads();
        if (tid < 32) {
            float v = sc[tid] + sc[tid + 32];
            v += __shfl_down_sync(0xffffffffu, v, 16);
            v += __shfl_down_sync(0xffffffffu, v, 8);
            v += __shfl_down_sync(0xffffffffu, v, 4);
            v += __shfl_down_sync(0xffffffffu, v, 2);
            v += __shfl_down_sync(0xffffffffu, v, 1);
            if (tid == 0) *sinv = __fdividef(1.f, v);
        }
        __syncthreads();
        if (tid < Lq) sc[tid] *= *sinv;
        __syncthreads();
        {
            int j0 = tid * 2;
            const __nv_bfloat162* Sc =
                reinterpret_cast<const __nv_bfloat162*>(g_S + (long)b * Lq * Hq + j0);
            float ax = 0.f, ay = 0.f;
#pragma unroll 16
            for (int l2 = 0; l2 < Lq; l2++) {
                float2 v = __bfloat1622float2(__ldg(&Sc[(long)l2 * 256]));
                ax = fmaf(sc[l2], v.x, ax);
                ay = fmaf(sc[l2], v.y, ay);
            }
            __nv_bfloat162* cd =
                reinterpret_cast<__nv_bfloat162*>(&g_ctxb[s & 1][(long)b * Hq + j0]);
            *cd = __floats2bfloat162_rn(ax, ay);
        }
    }
}

// ============================================================
// standalone bf16 GEMM (for decoder init; tanh epilogue)
// ============================================================
__global__ __launch_bounds__(256) void hgemm_k(
    const __nv_bfloat16* __restrict__ A0, int lda,
    const __nv_bfloat16* __restrict__ W0, int ldw0,
    const __nv_bfloat16* __restrict__ A1, const __nv_bfloat16* __restrict__ W1, int ldw1,
    int npairs,
    const float* __restrict__ bias, int N,
    float* __restrict__ outRaw, float* __restrict__ outTanhF,
    __nv_bfloat16* __restrict__ outBF)
{
    __shared__ __nv_bfloat16 As[128 * LSTRIDE];
    __shared__ __nv_bfloat16 Bs[128 * LSTRIDE];
    const int tid = threadIdx.x, lane = tid & 31, wid = tid >> 5;
    const int m0 = (wid >> 2) * 64, warp_n = wid & 3;
    const int mblk0 = blockIdx.x * 128, nblk0 = blockIdx.y * 128;

    float c[4][4][4];
#pragma unroll
    for (int mi = 0; mi < 4; mi++)
#pragma unroll
        for (int ni = 0; ni < 4; ni++)
#pragma unroll
            for (int q = 0; q < 4; q++) c[mi][ni][q] = 0.f;

    const unsigned as_base = (unsigned)__cvta_generic_to_shared(As);
    const unsigned bs_base = (unsigned)__cvta_generic_to_shared(Bs);
    const int ldrow = tid >> 3, ldc8 = (tid & 7) * 8;

    uint4 ra[4], rb[4];
    const int total = npairs * 8;
    auto fetch = [&](int ch) {
        int p = ch >> 3, k0 = (ch & 7) * 64;
        const __nv_bfloat16* A = (p == 0) ? A0 : A1;
        const __nv_bfloat16* W = (p == 0) ? W0 : W1;
        int ldw = (p == 0) ? ldw0 : ldw1;
#pragma unroll
        for (int q = 0; q < 4; q++) {
            int row = q * 32 + ldrow;
            int gm = mblk0 + row;
            ra[q] = *reinterpret_cast<const uint4*>(&A[(long)gm * lda + k0 + ldc8]);
            rb[q] = *reinterpret_cast<const uint4*>(&W[(long)(nblk0 + row) * ldw + k0 + ldc8]);
        }
    };
    fetch(0);
    for (int ch = 0; ch < total; ch++) {
        __syncthreads();
#pragma unroll
        for (int q = 0; q < 4; q++) {
            int row = q * 32 + ldrow;
            *reinterpret_cast<uint4*>(&As[row * LSTRIDE + ldc8]) = ra[q];
            *reinterpret_cast<uint4*>(&Bs[row * LSTRIDE + ldc8]) = rb[q];
        }
        __syncthreads();
        if (ch + 1 < total) fetch(ch + 1);
#pragma unroll
        for (int ks = 0; ks < 4; ks++) {
            int koff = ks * 16;
            unsigned a[4][4], b[4][2];
#pragma unroll
            for (int mi = 0; mi < 4; mi++) {
                int r = m0 + mi * 16 + (lane & 15);
                int ccol = koff + (lane >> 4) * 8;
                ldsm4(a[mi], as_base + (unsigned)(r * LSTRIDE + ccol) * 2u);
            }
#pragma unroll
            for (int ni = 0; ni < 4; ni++) {
                int r = warp_n * 32 + ni * 8 + (lane & 7);
                int ccol = koff + ((lane >> 3) & 1) * 8;
                ldsm2(b[ni], bs_base + (unsigned)(r * LSTRIDE + ccol) * 2u);
            }
#pragma unroll
            for (int mi = 0; mi < 4; mi++)
#pragma unroll
                for (int ni = 0; ni < 4; ni++) mma16816(c[mi][ni], a[mi], b[ni]);
        }
    }

#pragma unroll
    for (int mi = 0; mi < 4; mi++)
#pragma unroll
        for (int ni = 0; ni < 4; ni++)
#pragma unroll
            for (int t2 = 0; t2 < 2; t2++) {
                int gm = mblk0 + m0 + mi * 16 + (lane >> 2) + 8 * t2;
#pragma unroll
                for (int u = 0; u < 2; u++) {
                    int n = nblk0 + warp_n * 32 + ni * 8 + 2 * (lane & 3) + u;
                    float v = c[mi][ni][2 * t2 + u];
                    long oi = (long)gm * N + n;
                    if (bias) v += bias[n];
                    if (outRaw) outRaw[oi] = v;
                    float tv = v;
                    if (outTanhF) { tv = tanhf(v); outTanhF[oi] = tv; }
                    if (outBF) outBF[oi] = __float2bfloat16_rn(outTanhF ? tv : v);
                }
            }
}

// ---------------- fused setup launch 1 ----------------
__device__ __forceinline__ void cvt8(const float* __restrict__ src,
                                     __nv_bfloat16* __restrict__ dst, long i)
{
    float4 v0 = *reinterpret_cast<const float4*>(src + i);
    float4 v1 = *reinterpret_cast<const float4*>(src + i + 4);
    __nv_bfloat162 r0 = __floats2bfloat162_rn(v0.x, v0.y);
    __nv_bfloat162 r1 = __floats2bfloat162_rn(v0.z, v0.w);
    __nv_bfloat162 r2 = __floats2bfloat162_rn(v1.x, v1.y);
    __nv_bfloat162 r3 = __floats2bfloat162_rn(v1.z, v1.w);
    uint4 o;
    o.x = *reinterpret_cast<unsigned*>(&r0);
    o.y = *reinterpret_cast<unsigned*>(&r1);
    o.z = *reinterpret_cast<unsigned*>(&r2);
    o.w = *reinterpret_cast<unsigned*>(&r3);
    *reinterpret_cast<uint4*>(dst + i) = o;
}

// grid = 27072: [0,256) zero | [256,8448) gather_src | [8448,14464) gather_trg |
// [14464,16512) f2bf_enc | [16512,26560) f2bf_dec | [26560,27072) transp_hidw
__global__ __launch_bounds__(256) void setup1_k(
    const int* __restrict__ src_tokens, const int* __restrict__ trg_tokens,
    const float* __restrict__ src_emb, const float* __restrict__ trg_emb,
    const float* __restrict__ w0, const float* __restrict__ w1,
    const float* __restrict__ w2, const float* __restrict__ w3,
    const float* __restrict__ dWih, const float* __restrict__ dWhh,
    const float* __restrict__ hidW, const float* __restrict__ initW,
    const float* __restrict__ outW)
{
    const int blk = blockIdx.x;
    const int tid = threadIdx.x;
    if (blk < 256) {
        int i = blk * 256 + tid;
        if (i < HB) {
            g_h1b[0][i] = __float2bfloat16(0.f);
            g_h2b[0][i] = __float2bfloat16(0.f);
            g_c1[i] = 0.f; g_c2[i] = 0.f;
        }
        if (blk == 0 && tid < 80) g_eflag[tid] = 0u;
        if (blk == 1 && tid < 64) g_dflag[tid] = 0u;
    } else if (blk < 8448) {
        int m = blk - 256;
        int tok = src_tokens[m];
        const float2* src = reinterpret_cast<const float2*>(src_emb + (long)tok * Eq);
        __nv_bfloat162* dst = reinterpret_cast<__nv_bfloat162*>(g_xsB + (long)m * Eq);
        float2 v = src[tid];
        dst[tid] = __floats2bfloat162_rn(v.x, v.y);
    } else if (blk < 14464) {
        int m = blk - 8448;
        int s = m >> 7, b = m & 127;
        int tok = trg_tokens[b * Tq + s];
        const float2* src = reinterpret_cast<const float2*>(trg_emb + (long)tok * Eq);
        __nv_bfloat162* dst = reinterpret_cast<__nv_bfloat162*>(g_vembB + (long)m * Eq);
        float2 v = src[tid];
        dst[tid] = __floats2bfloat162_rn(v.x, v.y);
    } else if (blk < 16512) {
        int b2 = blk - 14464;
        int seg = b2 >> 9;
        long i = ((long)(b2 & 511) * 256 + tid) * 8;
        const float* srcs[4] = {w0, w1, w2, w3};
        __nv_bfloat16* dsts[4] = {g_Wih0b, g_Whh0b, g_Wih1b, g_Whh1b};
        cvt8(srcs[seg], dsts[seg], i);
    } else if (blk < 26560) {
        int b = blk - 16512;
        const float* src; __nv_bfloat16* dst; int rb;
        if (b < 1024)      { src = dWih;  dst = g_dWihb;  rb = b; }
        else if (b < 1536) { src = dWhh;  dst = g_dWhhb;  rb = b - 1024; }
        else if (b < 1792) { src = hidW;  dst = g_hidWb;  rb = b - 1536; }
        else if (b < 2048) { src = initW; dst = g_initWb; rb = b - 1792; }
        else               { src = outW;  dst = g_outWb;  rb = b - 2048; }
        long i = ((long)rb * 256 + tid) * 8;
        cvt8(src, dst, i);
    } else {
        __shared__ float tile[32][33];
        int b = blk - 26560;
        int k0 = (b & 31) * 32;
        int j0 = (b >> 5) * 32;
        int tx = tid & 31, ty = tid >> 5;
#pragma unroll
        for (int m = 0; m < 4; m++)
            tile[ty + 8 * m][tx] = hidW[(long)(j0 + ty + 8 * m) * 1024 + k0 + tx];
        __syncthreads();
#pragma unroll
        for (int m = 0; m < 4; m++)
            g_hidWT[(long)(k0 + ty + 8 * m) * 512 + j0 + tx] =
                __float2bfloat16_rn(tile[tx][ty + 8 * m]);
    }
}

// ---------------- fused setup launch 2: M-GEMM || G0-GEMM ----------------
// grid = 1152: [0,128) M tiles (16x8) | [128,1152) G0 tiles (64x16)
__global__ __launch_bounds__(256) void setup2_k(const float* __restrict__ enc_b0)
{
    __shared__ __nv_bfloat16 As[128 * LSTRIDE];
    __shared__ __nv_bfloat16 Bs[128 * LSTRIDE];
    const int blk = blockIdx.x;
    if (blk < 128) {
        int mt = blk >> 3, nt = blk & 7;
        hg_tile(g_dWihb + 512, 1024, g_hidWT, 512,
                nullptr, 1024, g_M, nullptr, mt * 128, nt * 128, As, Bs);
    } else {
        int idx = blk - 128;
        int mt = idx >> 4, nt = idx & 15;
        hg_tile(g_xsB, 512, g_Wih0b, 512,
                enc_b0, G4, nullptr, g_G0, mt * 128, nt * 128, As, Bs);
    }
}

// ---------------- fold ----------------
__global__ void fold_k(const float* __restrict__ dWhh,
                       const float* __restrict__ dWih,
                       const float* __restrict__ hid_b)
{
    int b = blockIdx.x;
    if (b < 2048) {
        int n = b;
#pragma unroll
        for (int kk = 0; kk < 2; kk++) {
            int k = threadIdx.x + kk * 256;
            g_Wdh[(long)n * 512 + k] =
                __float2bfloat16_rn(dWhh[(long)n * 512 + k] + g_M[(long)n * 1024 + k]);
            g_Wctx[(long)n * 512 + k] =
                __float2bfloat16_rn(g_M[(long)n * 1024 + 512 + k]);
        }
    } else {
        int n = (b - 2048) * 256 + threadIdx.x;
        float acc = 0.f;
        for (int j = 0; j < 512; j++)
            acc = fmaf(dWih[(long)n * 1024 + 512 + j], hid_b[j], acc);
        g_bias2[n] = acc;
    }
}

__global__ void conv_c_k()
{
    int i = blockIdx.x * 256 + threadIdx.x;
    if (i < HB) {
        g_c1b[i] = __float2bfloat16_rn(g_c1[i]);
        g_c2b[i] = __float2bfloat16_rn(g_c2[i]);
    }
}

__global__ __launch_bounds__(256) void reduce_k(float* __restrict__ out)
{
    __shared__ float sm[256];
    float t = 0.f;
    for (int i = threadIdx.x; i < (Tq - 1) * Bq; i += 256) t += g_nllbuf[i];
    sm[threadIdx.x] = t;
    __syncthreads();
    for (int st = 128; st > 0; st >>= 1) {
        if (threadIdx.x < st) sm[threadIdx.x] += sm[threadIdx.x + st];
        __syncthreads();
    }
    if (threadIdx.x == 0) out[0] = sm[0];
}

// ---------------- launch ----------------
extern "C" void kernel_launch(void* const* d_in, const int* in_sizes, int n_in,
                              void* d_out, int out_size)
{
    const int*   src_tokens = (const int*)d_in[0];
    const int*   src_lens   = (const int*)d_in[1];
    const int*   trg_tokens = (const int*)d_in[2];
    const int*   trg_lens   = (const int*)d_in[3];
    const float* src_emb    = (const float*)d_in[4];
    const float* trg_emb    = (const float*)d_in[5];
    const float* enc_Wih0   = (const float*)d_in[6];
    const float* enc_Whh0   = (const float*)d_in[7];
    const float* enc_b0     = (const float*)d_in[8];
    const float* enc_Wih1   = (const float*)d_in[9];
    const float* enc_Whh1   = (const float*)d_in[10];
    const float* enc_b1     = (const float*)d_in[11];
    const float* dec_Wih    = (const float*)d_in[12];
    const float* dec_Whh    = (const float*)d_in[13];
    const float* dec_b      = (const float*)d_in[14];
    const float* hid_W      = (const float*)d_in[15];
    const float* hid_b      = (const float*)d_in[16];
    const float* out_W      = (const float*)d_in[17];
    const float* out_b      = (const float*)d_in[18];
    const float* init_W     = (const float*)d_in[19];
    const float* init_b     = (const float*)d_in[20];

    float *dc, *dh;
    __nv_bfloat16 *initWb, *c1b, *c2b, *dhb0;
    cudaGetSymbolAddress((void**)&dc, g_dc);
    cudaGetSymbolAddress((void**)&dh, g_dh);
    cudaGetSymbolAddress((void**)&initWb, g_initWb);
    cudaGetSymbolAddress((void**)&c1b, g_c1b);
    cudaGetSymbolAddress((void**)&c2b, g_c2b);
    cudaGetSymbolAddress((void**)&dhb0, g_dhb);

    const int cb = (HB + 255) / 256;

    // fused setup
    setup1_k<<<27072, 256>>>(src_tokens, trg_tokens, src_emb, trg_emb,
                             enc_Wih0, enc_Whh0, enc_Wih1, enc_Whh1,
                             dec_Wih, dec_Whh, hid_W, init_W, out_W);
    setup2_k<<<1152, 256>>>(enc_b0);
    fold_k<<<2056, 256>>>(dec_Whh, dec_Wih, hid_b);

    // ---------------- encoder: 2 steps/launch + GV riders ----------------
    for (int k = 0; k <= Lq / 2; k++)
        enc2_k<<<88, 256>>>(k, src_lens, enc_b1, dec_b);

    // decoder init: c0 = [c1,c2] @ init_W^T + init_b ; h0 = tanh(c0)
    conv_c_k<<<cb, 256>>>();
    hgemm_k<<<dim3(1, Hq / 128), 256>>>(
        c1b, 512, initWb, 1024, c2b, initWb + 512, 1024, 2,
        init_b, Hq, dc, dh, dhb0);

    // ---------------- decoder: 1 launch per step ----------------
    for (int s = 0; s <= Tq + 1; s++)
        dec1_k<<<274, 256>>>(s, trg_tokens, src_lens, trg_lens, out_b, hid_b);

    reduce_k<<<1, 256>>>((float*)d_out);
}